// round 15
// baseline (speedup 1.0000x reference)
#include <cuda_runtime.h>
#include <cuda_fp16.h>
#include <cstdint>

#define Bn   16
#define Cc   512
#define HWn  1024
#define NH   8
#define DH   64

// Scratch (static device arrays — no cudaMalloc). All fp16.
__device__ __half g_ht[Bn * HWn * Cc];               // h^T  [b][hw][c]
__device__ __half g_qkv[Bn * NH * 3 * HWn * DH];     // q,k: [bh][p][s][c]; v: [bh][2][c][s]
__device__ __half g_attn[Bn * HWn * Cc];             // attn out [b][s][c]
__device__ __half g_wqkv[3 * Cc * Cc];               // fp16 copy of w_qkv
__device__ __half g_wproj[Cc * Cc];                  // fp16 copy of w_proj

// q is pre-scaled by softmax_scale * log2(e) so scores land in log2 domain
#define QSCALE (0.044194173824159216f * 1.4426950408889634f)

// ---------------------------------------------------------------------------
// PTX helpers
// ---------------------------------------------------------------------------
__device__ __forceinline__ uint32_t smem_u32(const void* p) {
    uint32_t a;
    asm("{ .reg .u64 t; cvta.to.shared.u64 t, %1; cvt.u32.u64 %0, t; }" : "=r"(a) : "l"(p));
    return a;
}
__device__ __forceinline__ uint32_t h2ex2(uint32_t x) {
    uint32_t r;
    asm("ex2.approx.f16x2 %0, %1;" : "=r"(r) : "r"(x));
    return r;
}
__device__ __forceinline__ uint32_t h2add(uint32_t a, uint32_t b) {
    uint32_t r;
    asm("add.rn.f16x2 %0, %1, %2;" : "=r"(r) : "r"(a), "r"(b));
    return r;
}
__device__ __forceinline__ float2 h2f2(uint32_t u) {
    __half2 h;
    memcpy(&h, &u, 4);
    return __half22float2(h);
}
#define CP16(dst, src)                                                        \
    asm volatile("cp.async.cg.shared.global [%0], [%1], 16;"                  \
                 :: "r"(dst), "l"(src))
#define CP_COMMIT() asm volatile("cp.async.commit_group;" ::: "memory")
#define CP_WAIT2()  asm volatile("cp.async.wait_group 2;" ::: "memory")
#define CP_WAIT1()  asm volatile("cp.async.wait_group 1;" ::: "memory")
#define CP_WAIT0()  asm volatile("cp.async.wait_group 0;" ::: "memory")

#define LDSM_X4(r0, r1, r2, r3, a)                                            \
    asm volatile("ldmatrix.sync.aligned.m8n8.x4.shared.b16 {%0,%1,%2,%3}, [%4];" \
        : "=r"(r0), "=r"(r1), "=r"(r2), "=r"(r3) : "r"(a))

#define MMA_F16(c, a, bfr)                                                    \
    asm volatile(                                                             \
        "mma.sync.aligned.m16n8k16.row.col.f32.f16.f16.f32 "                  \
        "{%0,%1,%2,%3}, {%4,%5,%6,%7}, {%8,%9}, {%0,%1,%2,%3};"               \
        : "+f"((c)[0]), "+f"((c)[1]), "+f"((c)[2]), "+f"((c)[3])              \
        : "r"((a)[0]), "r"((a)[1]), "r"((a)[2]), "r"((a)[3]),                 \
          "r"((bfr)[0]), "r"((bfr)[1]))

__device__ __forceinline__ uint32_t pack_h2(float lo, float hi) {
    __half2 h = __floats2half2_rn(lo, hi);
    uint32_t u;
    memcpy(&u, &h, 4);
    return u;
}

// ---------------------------------------------------------------------------
// Weight fp32 -> fp16 converter (both weights, one launch)
// ---------------------------------------------------------------------------
__global__ __launch_bounds__(256) void cvt_w_kernel(const float* __restrict__ wq,
                                                    const float* __restrict__ wp) {
    int i = (blockIdx.x * 256 + threadIdx.x) * 4;
    if (i < 3 * Cc * Cc) {
        float4 v = *(const float4*)(wq + i);
        *(__half2*)(g_wqkv + i)     = __floats2half2_rn(v.x, v.y);
        *(__half2*)(g_wqkv + i + 2) = __floats2half2_rn(v.z, v.w);
    } else {
        int j = i - 3 * Cc * Cc;
        float4 v = *(const float4*)(wp + j);
        *(__half2*)(g_wproj + j)     = __floats2half2_rn(v.x, v.y);
        *(__half2*)(g_wproj + j + 2) = __floats2half2_rn(v.z, v.w);
    }
}

// ---------------------------------------------------------------------------
// fp16 warp-MMA GEMM mainloop: D[128x128] = A[128x512]*B[128x512]^T.
// 4 warps (2m x 2n), warp tile 64x64 -> MMA:LDSM = 4:1 (crossbar relief).
// 128 threads, k-tile 64 halves, 3-stage cp.async. 2 blocks/SM (216KB smem).
// Stage = (A 128 + B 128 rows) x 144B = 36864 B; 3 stages = 110592 B.
// ---------------------------------------------------------------------------
__device__ __forceinline__ void gemm_fill(uint32_t sb, int st,
                                          const __half* __restrict__ Arow,
                                          const __half* __restrict__ Brow,
                                          int k0, int tid) {
    const uint32_t so = sb + (uint32_t)st * 36864u;
    #pragma unroll
    for (int i = 0; i < 8; i++) {
        int id = tid + i * 128;           // 0..1023
        int r = id >> 3, q = id & 7;      // 128 rows x 8x16B
        CP16(so + (uint32_t)(r * 144 + q * 16),
             Arow + (size_t)r * Cc + k0 + q * 8);
        CP16(so + 18432u + (uint32_t)(r * 144 + q * 16),
             Brow + (size_t)r * Cc + k0 + q * 8);
    }
}

__device__ __forceinline__ void gemm_mainloop(const __half* __restrict__ Arow,
                                              const __half* __restrict__ Brow,
                                              float acc[4][8][4]) {
    extern __shared__ char gsm[];
    uint32_t sb = smem_u32(gsm);
    const int tid = threadIdx.x;
    const int warp = tid >> 5, lane = tid & 31;
    const int wm = warp & 1, wn = warp >> 1;
    const int lrow = (lane & 7) + ((lane >> 3) & 1) * 8;   // A: m within 16
    const int lka  = ((lane >> 4) & 1) * 8;                // A: k halves
    const int brow = (lane & 7) + ((lane >> 4) & 1) * 8;   // B: n within 16
    const int lkb  = ((lane >> 3) & 1) * 8;
    const uint32_t aBase = sb + (uint32_t)((wm * 64 + lrow) * 144 + lka * 2);
    const uint32_t bBase = sb + 18432u + (uint32_t)((wn * 64 + brow) * 144 + lkb * 2);

    #pragma unroll
    for (int mi = 0; mi < 4; mi++)
        #pragma unroll
        for (int ni = 0; ni < 8; ni++)
            #pragma unroll
            for (int c = 0; c < 4; c++) acc[mi][ni][c] = 0.f;

    gemm_fill(sb, 0, Arow, Brow, 0, tid);
    CP_COMMIT();
    gemm_fill(sb, 1, Arow, Brow, 64, tid);
    CP_COMMIT();

    #pragma unroll 1
    for (int it = 0; it < 8; it++) {
        if (it < 7) { CP_WAIT1(); } else { CP_WAIT0(); }
        __syncthreads();
        if (it + 2 < 8) {
            gemm_fill(sb, (it + 2) % 3, Arow, Brow, (it + 2) * 64, tid);
            CP_COMMIT();
        }
        const uint32_t so = (uint32_t)((it % 3) * 36864);
        #pragma unroll
        for (int kk = 0; kk < 4; kk++) {
            uint32_t af[4][4], bf[8][2];
            #pragma unroll
            for (int mi = 0; mi < 4; mi++)
                LDSM_X4(af[mi][0], af[mi][1], af[mi][2], af[mi][3],
                        aBase + so + mi * 2304 + kk * 32);
            #pragma unroll
            for (int p = 0; p < 4; p++) {
                uint32_t r0, r1, r2, r3;
                LDSM_X4(r0, r1, r2, r3, bBase + so + p * 2304 + kk * 32);
                bf[2 * p][0] = r0; bf[2 * p][1] = r1;
                bf[2 * p + 1][0] = r2; bf[2 * p + 1][1] = r3;
            }
            #pragma unroll
            for (int mi = 0; mi < 4; mi++)
                #pragma unroll
                for (int ni = 0; ni < 8; ni++)
                    MMA_F16(acc[mi][ni], af[mi], bf[ni]);
        }
    }
}

// ---------------------------------------------------------------------------
// Kernel 1: GroupNorm -> g_ht[b][hw][c] (fp16). Single-tile, 3 barriers.
// ---------------------------------------------------------------------------
__global__ __launch_bounds__(256) void gn_kernel(const float* __restrict__ x,
                                                 const float* __restrict__ gamma,
                                                 const float* __restrict__ beta) {
    extern __shared__ float sx[];            // [16][1032]
    __shared__ float rs_[8], rss_[8];
    __shared__ float ga_s[16], be_s[16];

    int b = blockIdx.x >> 5;
    int g = blockIdx.x & 31;
    int tid = threadIdx.x;
    size_t base = (size_t)(b * Cc + g * 16) * HWn;
    const float4* xp = (const float4*)(x + base);

    float s = 0.f, ss = 0.f;
    for (int i = tid; i < 4096; i += 256) {
        float4 v = xp[i];
        int c = i >> 8, hw4 = i & 255;
        *(float4*)&sx[c * 1032 + hw4 * 4] = v;
        s  += v.x + v.y + v.z + v.w;
        ss += v.x * v.x + v.y * v.y + v.z * v.z + v.w * v.w;
    }
    #pragma unroll
    for (int o = 16; o; o >>= 1) {
        s  += __shfl_xor_sync(0xffffffffu, s, o);
        ss += __shfl_xor_sync(0xffffffffu, ss, o);
    }
    int wid = tid >> 5, lid = tid & 31;
    if (lid == 0) { rs_[wid] = s; rss_[wid] = ss; }
    __syncthreads();
    if (tid < 32) {
        s = rs_[lid & 7]; ss = rss_[lid & 7];
        #pragma unroll
        for (int o = 4; o; o >>= 1) {
            s  += __shfl_xor_sync(0xffffffffu, s, o);
            ss += __shfl_xor_sync(0xffffffffu, ss, o);
        }
        if (lid == 0) { rs_[0] = s; rss_[0] = ss; }
    }
    __syncthreads();
    float mean = rs_[0] * (1.f / 16384.f);
    float var  = rss_[0] * (1.f / 16384.f) - mean * mean;
    float inv  = rsqrtf(var + 1e-5f);
    if (tid < 16) {
        float ga = gamma[g * 16 + tid] * inv;
        ga_s[tid] = ga;
        be_s[tid] = beta[g * 16 + tid] - mean * ga;
    }
    __syncthreads();

    __half* outb = g_ht + (size_t)b * HWn * Cc + g * 16;
    for (int hw = tid; hw < HWn; hw += 256) {
        uint32_t pk[8];
        #pragma unroll
        for (int cp = 0; cp < 8; cp++) {
            float v0 = sx[(2 * cp) * 1032 + hw]     * ga_s[2 * cp]     + be_s[2 * cp];
            float v1 = sx[(2 * cp + 1) * 1032 + hw] * ga_s[2 * cp + 1] + be_s[2 * cp + 1];
            pk[cp] = pack_h2(v0, v1);
        }
        __half* dst = outb + (size_t)hw * Cc;
        *(uint4*)dst       = make_uint4(pk[0], pk[1], pk[2], pk[3]);
        *(uint4*)(dst + 8) = make_uint4(pk[4], pk[5], pk[6], pk[7]);
    }
}

// ---------------------------------------------------------------------------
// Kernel 2: qkv GEMM (M = s rows of h^T, N = o rows of W, 128x128 blocks,
// 4 warps x 64x64). q pre-scaled by QSCALE; q,k -> [s][c]; v -> [c][s].
// ---------------------------------------------------------------------------
__global__ __launch_bounds__(128) void qkv_mma_kernel(const float* __restrict__ bias) {
    int b = blockIdx.z, m0 = blockIdx.x * 128, n0 = blockIdx.y * 128;
    const __half* Arow = g_ht + ((size_t)b * HWn + m0) * Cc;
    const __half* Brow = g_wqkv + (size_t)n0 * Cc;
    float acc[4][8][4];
    gemm_mainloop(Arow, Brow, acc);

    const int warp = threadIdx.x >> 5, lane = threadIdx.x & 31;
    const int wm = warp & 1, wn = warp >> 1;
    const int g = lane >> 2, tig = lane & 3;
    #pragma unroll
    for (int mi = 0; mi < 4; mi++) {
        #pragma unroll
        for (int h = 0; h < 2; h++) {
            int s = m0 + wm * 64 + mi * 16 + g + h * 8;
            #pragma unroll
            for (int ni = 0; ni < 8; ni++) {
                int o = n0 + wn * 64 + ni * 8 + 2 * tig;
                float2 bv = *(const float2*)&bias[o];
                float v0 = acc[mi][ni][h * 2 + 0] + bv.x;
                float v1 = acc[mi][ni][h * 2 + 1] + bv.y;
                int head = o / 192, rem = o - head * 192;
                int part = rem >> 6, c = rem & 63;
                __half* base = g_qkv + (size_t)((b * NH + head) * 3 + part) * HWn * DH;
                if (part == 0) {
                    *(__half2*)(base + (size_t)s * DH + c) =
                        __floats2half2_rn(v0 * QSCALE, v1 * QSCALE);
                } else if (part == 1) {
                    *(__half2*)(base + (size_t)s * DH + c) = __floats2half2_rn(v0, v1);
                } else {
                    base[(size_t)c * HWn + s]       = __float2half_rn(v0);
                    base[(size_t)(c + 1) * HWn + s] = __float2half_rn(v1);
                }
            }
        }
    }
}

// ---------------------------------------------------------------------------
// Kernel 3: flash attention (R14). 128-query blocks, 4 warps x m32,
// 4-stage cp.async K/V, Q frags from gmem, exp2 softmax w/o max.
// Smem 73728 B -> 2 blocks/SM.
// ---------------------------------------------------------------------------
__global__ __launch_bounds__(128) void attn_mma_kernel() {
    extern __shared__ char asmem[];
    uint32_t sb = smem_u32(asmem);

    int bh = blockIdx.y;
    int q0 = blockIdx.x << 7;
    int tid = threadIdx.x;
    int w = tid >> 5, lane = tid & 31;
    int g = lane >> 2, tig = lane & 3;

    const __half* qp = g_qkv + ((size_t)bh * 3 * HWn + q0) * DH;
    const __half* kp = g_qkv + (size_t)(bh * 3 + 1) * HWn * DH;
    const __half* vp = g_qkv + (size_t)(bh * 3 + 2) * HWn * DH;  // [dh][s]

    const int brow = (lane & 7) + ((lane >> 4) & 1) * 8;
    const int lkb  = ((lane >> 3) & 1) * 8;
    const uint32_t kAddr = sb + (uint32_t)(brow * 144 + lkb * 2);
    const uint32_t vAddr = sb + 36864u + (uint32_t)(brow * 144 + lkb * 2);

    #pragma unroll
    for (int st = 0; st < 3; st++) {
        const __half* kpt = kp + (size_t)st * 64 * DH;
        const __half* vpt = vp + st * 64;
        #pragma unroll
        for (int i = 0; i < 4; i++) {
            int id = tid + i * 128;
            int r = id >> 3, q = id & 7;
            CP16(sb + (uint32_t)(st * 9216 + r * 144 + q * 16),
                 kpt + (size_t)r * DH + q * 8);
            CP16(sb + 36864u + (uint32_t)(st * 9216 + r * 144 + q * 16),
                 vpt + (size_t)r * HWn + q * 8);
        }
        CP_COMMIT();
    }

    uint32_t qf[2][4][4];
    #pragma unroll
    for (int mi = 0; mi < 2; mi++) {
        const __half* qr  = qp + (size_t)(w * 32 + mi * 16 + g) * DH + 2 * tig;
        const __half* qr8 = qr + 8 * DH;
        #pragma unroll
        for (int kk = 0; kk < 4; kk++) {
            qf[mi][kk][0] = *(const uint32_t*)(qr  + kk * 16);
            qf[mi][kk][1] = *(const uint32_t*)(qr8 + kk * 16);
            qf[mi][kk][2] = *(const uint32_t*)(qr  + kk * 16 + 8);
            qf[mi][kk][3] = *(const uint32_t*)(qr8 + kk * 16 + 8);
        }
    }

    float oacc[2][8][4];
    #pragma unroll
    for (int mi = 0; mi < 2; mi++)
        #pragma unroll
        for (int nd = 0; nd < 8; nd++)
            #pragma unroll
            for (int c = 0; c < 4; c++) oacc[mi][nd][c] = 0.f;
    float l00 = 0.f, l01 = 0.f, l10 = 0.f, l11 = 0.f;

    #pragma unroll 1
    for (int t = 0; t < 16; t++) {
        if (t < 14)      { CP_WAIT2(); }
        else if (t == 14){ CP_WAIT1(); }
        else             { CP_WAIT0(); }
        __syncthreads();
        if (t + 3 < 16) {
            int st3 = (t + 3) & 3;
            const __half* kpt = kp + (size_t)(t + 3) * 64 * DH;
            const __half* vpt = vp + (t + 3) * 64;
            #pragma unroll
            for (int i = 0; i < 4; i++) {
                int id = tid + i * 128;
                int r = id >> 3, q = id & 7;
                CP16(sb + (uint32_t)(st3 * 9216 + r * 144 + q * 16),
                     kpt + (size_t)r * DH + q * 8);
                CP16(sb + 36864u + (uint32_t)(st3 * 9216 + r * 144 + q * 16),
                     vpt + (size_t)r * HWn + q * 8);
            }
            CP_COMMIT();
        }
        const uint32_t so = (uint32_t)((t & 3) * 9216);

        float sacc[2][8][4];
        #pragma unroll
        for (int mi = 0; mi < 2; mi++)
            #pragma unroll
            for (int ni = 0; ni < 8; ni++)
                #pragma unroll
                for (int c = 0; c < 4; c++) sacc[mi][ni][c] = 0.f;
        #pragma unroll
        for (int kk = 0; kk < 4; kk++) {
            #pragma unroll
            for (int p = 0; p < 4; p++) {
                uint32_t r0, r1, r2, r3;
                LDSM_X4(r0, r1, r2, r3, kAddr + so + p * 2304 + kk * 32);
                uint32_t b0[2] = {r0, r1}, b1[2] = {r2, r3};
                #pragma unroll
                for (int mi = 0; mi < 2; mi++) {
                    MMA_F16(sacc[mi][2 * p],     qf[mi][kk], b0);
                    MMA_F16(sacc[mi][2 * p + 1], qf[mi][kk], b1);
                }
            }
        }

        uint32_t ph[2][8][2];
        #pragma unroll
        for (int mi = 0; mi < 2; mi++)
            #pragma unroll
            for (int ni = 0; ni < 8; ni++) {
                ph[mi][ni][0] = h2ex2(pack_h2(sacc[mi][ni][0], sacc[mi][ni][1]));
                ph[mi][ni][1] = h2ex2(pack_h2(sacc[mi][ni][2], sacc[mi][ni][3]));
            }
        #pragma unroll
        for (int mi = 0; mi < 2; mi++) {
            uint32_t t0 = h2add(h2add(h2add(ph[mi][0][0], ph[mi][1][0]),
                                      h2add(ph[mi][2][0], ph[mi][3][0])),
                                h2add(h2add(ph[mi][4][0], ph[mi][5][0]),
                                      h2add(ph[mi][6][0], ph[mi][7][0])));
            uint32_t t1 = h2add(h2add(h2add(ph[mi][0][1], ph[mi][1][1]),
                                      h2add(ph[mi][2][1], ph[mi][3][1])),
                                h2add(h2add(ph[mi][4][1], ph[mi][5][1]),
                                      h2add(ph[mi][6][1], ph[mi][7][1])));
            float2 f0 = h2f2(t0), f1 = h2f2(t1);
            float rs0 = f0.x + f0.y, rs1 = f1.x + f1.y;
            rs0 += __shfl_xor_sync(0xffffffffu, rs0, 1);
            rs0 += __shfl_xor_sync(0xffffffffu, rs0, 2);
            rs1 += __shfl_xor_sync(0xffffffffu, rs1, 1);
            rs1 += __shfl_xor_sync(0xffffffffu, rs1, 2);
            if (mi == 0) { l00 += rs0; l01 += rs1; }
            else         { l10 += rs0; l11 += rs1; }
        }

        #pragma unroll
        for (int kk = 0; kk < 4; kk++) {
            #pragma unroll
            for (int p = 0; p < 4; p++) {
                uint32_t r0, r1, r2, r3;
                LDSM_X4(r0, r1, r2, r3, vAddr + so + p * 2304 + kk * 32);
                uint32_t b0[2] = {r0, r1}, b1[2] = {r2, r3};
                #pragma unroll
                for (int mi = 0; mi < 2; mi++) {
                    uint32_t ap[4] = {ph[mi][2 * kk][0], ph[mi][2 * kk][1],
                                      ph[mi][2 * kk + 1][0], ph[mi][2 * kk + 1][1]};
                    MMA_F16(oacc[mi][2 * p],     ap, b0);
                    MMA_F16(oacc[mi][2 * p + 1], ap, b1);
                }
            }
        }
    }

    int bp  = bh & 15;
    int ch0 = (bh >> 4) << 6;
    #pragma unroll
    for (int mi = 0; mi < 2; mi++) {
        float il0 = 1.f / (mi == 0 ? l00 : l10);
        float il1 = 1.f / (mi == 0 ? l01 : l11);
        int s0 = q0 + w * 32 + mi * 16 + g;
        #pragma unroll
        for (int nd = 0; nd < 8; nd++) {
            int c = ch0 + nd * 8 + 2 * tig;
            *(__half2*)(g_attn + ((size_t)(bp * HWn + s0)) * Cc + c) =
                __floats2half2_rn(oacc[mi][nd][0] * il0, oacc[mi][nd][1] * il0);
            *(__half2*)(g_attn + ((size_t)(bp * HWn + s0 + 8)) * Cc + c) =
                __floats2half2_rn(oacc[mi][nd][2] * il1, oacc[mi][nd][3] * il1);
        }
    }
}

// ---------------------------------------------------------------------------
// Kernel 4: out = W_proj @ attn + bias + x (128x128 blocks, 4 warps x 64x64).
// ---------------------------------------------------------------------------
__global__ __launch_bounds__(128) void proj_mma_kernel(const float* __restrict__ bias,
                                                       const float* __restrict__ x,
                                                       float* __restrict__ out) {
    int b = blockIdx.z, o0 = blockIdx.x * 128, n0 = blockIdx.y * 128;
    const __half* Arow = g_wproj + (size_t)o0 * Cc;
    const __half* Brow = g_attn + ((size_t)b * HWn + n0) * Cc;
    float acc[4][8][4];
    gemm_mainloop(Arow, Brow, acc);

    const int warp = threadIdx.x >> 5, lane = threadIdx.x & 31;
    const int wm = warp & 1, wn = warp >> 1;
    const int g = lane >> 2, tig = lane & 3;
    #pragma unroll
    for (int mi = 0; mi < 4; mi++) {
        #pragma unroll
        for (int h = 0; h < 2; h++) {
            int o = o0 + wm * 64 + mi * 16 + g + h * 8;
            float bv = __ldg(bias + o);
            size_t rowoff = (size_t)(b * Cc + o) * HWn;
            #pragma unroll
            for (int ni = 0; ni < 8; ni++) {
                int s = n0 + wn * 64 + ni * 8 + 2 * tig;
                float2 xv = *(const float2*)&x[rowoff + s];
                float2 ov;
                ov.x = acc[mi][ni][h * 2 + 0] + bv + xv.x;
                ov.y = acc[mi][ni][h * 2 + 1] + bv + xv.y;
                *(float2*)&out[rowoff + s] = ov;
            }
        }
    }
}

// ---------------------------------------------------------------------------
extern "C" void kernel_launch(void* const* d_in, const int* in_sizes, int n_in,
                              void* d_out, int out_size) {
    const float* x      = (const float*)d_in[0];
    const float* gamma  = (const float*)d_in[1];
    const float* beta   = (const float*)d_in[2];
    const float* w_qkv  = (const float*)d_in[3];
    const float* b_qkv  = (const float*)d_in[4];
    const float* w_proj = (const float*)d_in[5];
    const float* b_proj = (const float*)d_in[6];
    float* out = (float*)d_out;

    const int GEMM_SMEM = 110592;    // 3 stages x (A+B) x 128x144B
    const int ATTN_SMEM = 73728;     // 4 x (K 9216) + 4 x (V 9216)
    const int GN_SMEM   = 66048;
    cudaFuncSetAttribute(qkv_mma_kernel,
                         cudaFuncAttributeMaxDynamicSharedMemorySize, GEMM_SMEM);
    cudaFuncSetAttribute(proj_mma_kernel,
                         cudaFuncAttributeMaxDynamicSharedMemorySize, GEMM_SMEM);
    cudaFuncSetAttribute(attn_mma_kernel,
                         cudaFuncAttributeMaxDynamicSharedMemorySize, ATTN_SMEM);
    cudaFuncSetAttribute(gn_kernel,
                         cudaFuncAttributeMaxDynamicSharedMemorySize, GN_SMEM);

    cvt_w_kernel<<<1024, 256>>>(w_qkv, w_proj);
    gn_kernel<<<Bn * 32, 256, GN_SMEM>>>(x, gamma, beta);
    qkv_mma_kernel<<<dim3(8, 12, Bn), 128, GEMM_SMEM>>>(b_qkv);
    attn_mma_kernel<<<dim3(HWn / 128, Bn * NH), 128, ATTN_SMEM>>>();
    proj_mma_kernel<<<dim3(4, 8, Bn), 128, GEMM_SMEM>>>(b_proj, x, out);
}

// round 16
// speedup vs baseline: 1.0581x; 1.0581x over previous
#include <cuda_runtime.h>
#include <cuda_fp16.h>
#include <cstdint>

#define Bn   16
#define Cc   512
#define HWn  1024
#define NH   8
#define DH   64

// Scratch (static device arrays — no cudaMalloc). All fp16.
__device__ __half g_ht[Bn * HWn * Cc];               // h^T  [b][hw][c]
__device__ __half g_qkv[Bn * NH * 3 * HWn * DH];     // q,k: [bh][p][s][c]; v: [bh][2][c][s]
__device__ __half g_attn[Bn * HWn * Cc];             // attn out [b][s][c]
__device__ __half g_wqkv[3 * Cc * Cc];               // fp16 copy of w_qkv
__device__ __half g_wproj[Cc * Cc];                  // fp16 copy of w_proj

// q is pre-scaled by softmax_scale * log2(e) so scores land in log2 domain
#define QSCALE (0.044194173824159216f * 1.4426950408889634f)

// ---------------------------------------------------------------------------
// PTX helpers
// ---------------------------------------------------------------------------
__device__ __forceinline__ uint32_t smem_u32(const void* p) {
    uint32_t a;
    asm("{ .reg .u64 t; cvta.to.shared.u64 t, %1; cvt.u32.u64 %0, t; }" : "=r"(a) : "l"(p));
    return a;
}
__device__ __forceinline__ uint32_t h2ex2(uint32_t x) {
    uint32_t r;
    asm("ex2.approx.f16x2 %0, %1;" : "=r"(r) : "r"(x));
    return r;
}
__device__ __forceinline__ uint32_t h2add(uint32_t a, uint32_t b) {
    uint32_t r;
    asm("add.rn.f16x2 %0, %1, %2;" : "=r"(r) : "r"(a), "r"(b));
    return r;
}
__device__ __forceinline__ float2 h2f2(uint32_t u) {
    __half2 h;
    memcpy(&h, &u, 4);
    return __half22float2(h);
}
#define CP16(dst, src)                                                        \
    asm volatile("cp.async.cg.shared.global [%0], [%1], 16;"                  \
                 :: "r"(dst), "l"(src))
#define CP_COMMIT() asm volatile("cp.async.commit_group;" ::: "memory")
#define CP_WAIT2()  asm volatile("cp.async.wait_group 2;" ::: "memory")
#define CP_WAIT1()  asm volatile("cp.async.wait_group 1;" ::: "memory")
#define CP_WAIT0()  asm volatile("cp.async.wait_group 0;" ::: "memory")

#define LDSM_X4(r0, r1, r2, r3, a)                                            \
    asm volatile("ldmatrix.sync.aligned.m8n8.x4.shared.b16 {%0,%1,%2,%3}, [%4];" \
        : "=r"(r0), "=r"(r1), "=r"(r2), "=r"(r3) : "r"(a))

#define MMA_F16(c, a, bfr)                                                    \
    asm volatile(                                                             \
        "mma.sync.aligned.m16n8k16.row.col.f32.f16.f16.f32 "                  \
        "{%0,%1,%2,%3}, {%4,%5,%6,%7}, {%8,%9}, {%0,%1,%2,%3};"               \
        : "+f"((c)[0]), "+f"((c)[1]), "+f"((c)[2]), "+f"((c)[3])              \
        : "r"((a)[0]), "r"((a)[1]), "r"((a)[2]), "r"((a)[3]),                 \
          "r"((bfr)[0]), "r"((bfr)[1]))

__device__ __forceinline__ uint32_t pack_h2(float lo, float hi) {
    __half2 h = __floats2half2_rn(lo, hi);
    uint32_t u;
    memcpy(&u, &h, 4);
    return u;
}

// ---------------------------------------------------------------------------
// fp16 warp-MMA GEMM mainloop (R14 config): D[128x128] = A[128x512]*B[128x512]^T
// 8 warps (2m x 4n), warp tile 64x32, k-tile 64 halves. 2 blocks/SM.
// Stage = (A 128 + B 128 rows) x 144B = 36864 B; 3 stages = 110592 B.
// ---------------------------------------------------------------------------
__device__ __forceinline__ void gemm_fill(uint32_t sb, int st,
                                          const __half* __restrict__ Arow,
                                          const __half* __restrict__ Brow,
                                          int k0, int tid) {
    const uint32_t so = sb + (uint32_t)st * 36864u;
    #pragma unroll
    for (int i = 0; i < 4; i++) {
        int id = tid + i * 256;           // 0..1023
        int r = id >> 3, q = id & 7;      // 128 rows x 8x16B
        CP16(so + (uint32_t)(r * 144 + q * 16),
             Arow + (size_t)r * Cc + k0 + q * 8);
        CP16(so + 18432u + (uint32_t)(r * 144 + q * 16),
             Brow + (size_t)r * Cc + k0 + q * 8);
    }
}

__device__ __forceinline__ void gemm_mainloop(const __half* __restrict__ Arow,
                                              const __half* __restrict__ Brow,
                                              float acc[4][4][4]) {
    extern __shared__ char gsm[];
    uint32_t sb = smem_u32(gsm);
    const int tid = threadIdx.x;
    const int warp = tid >> 5, lane = tid & 31;
    const int wm = warp & 1, wn = warp >> 1;
    const int lrow = (lane & 7) + ((lane >> 3) & 1) * 8;   // A: m within 16
    const int lka  = ((lane >> 4) & 1) * 8;                // A: k halves
    const int brow = (lane & 7) + ((lane >> 4) & 1) * 8;   // B: n within 16
    const int lkb  = ((lane >> 3) & 1) * 8;
    const uint32_t aBase = sb + (uint32_t)((wm * 64 + lrow) * 144 + lka * 2);
    const uint32_t bBase = sb + 18432u + (uint32_t)((wn * 32 + brow) * 144 + lkb * 2);

    #pragma unroll
    for (int mi = 0; mi < 4; mi++)
        #pragma unroll
        for (int ni = 0; ni < 4; ni++)
            #pragma unroll
            for (int c = 0; c < 4; c++) acc[mi][ni][c] = 0.f;

    gemm_fill(sb, 0, Arow, Brow, 0, tid);
    CP_COMMIT();
    gemm_fill(sb, 1, Arow, Brow, 64, tid);
    CP_COMMIT();

    #pragma unroll 1
    for (int it = 0; it < 8; it++) {
        if (it < 7) { CP_WAIT1(); } else { CP_WAIT0(); }
        __syncthreads();
        if (it + 2 < 8) {
            gemm_fill(sb, (it + 2) % 3, Arow, Brow, (it + 2) * 64, tid);
            CP_COMMIT();
        }
        const uint32_t so = (uint32_t)((it % 3) * 36864);
        #pragma unroll
        for (int kk = 0; kk < 4; kk++) {
            uint32_t af[4][4], bf[4][2];
            #pragma unroll
            for (int mi = 0; mi < 4; mi++)
                LDSM_X4(af[mi][0], af[mi][1], af[mi][2], af[mi][3],
                        aBase + so + mi * 2304 + kk * 32);
            #pragma unroll
            for (int p = 0; p < 2; p++) {
                uint32_t r0, r1, r2, r3;
                LDSM_X4(r0, r1, r2, r3, bBase + so + p * 2304 + kk * 32);
                bf[2 * p][0] = r0; bf[2 * p][1] = r1;
                bf[2 * p + 1][0] = r2; bf[2 * p + 1][1] = r3;
            }
            #pragma unroll
            for (int mi = 0; mi < 4; mi++)
                #pragma unroll
                for (int ni = 0; ni < 4; ni++)
                    MMA_F16(acc[mi][ni], af[mi], bf[ni]);
        }
    }
}

// ---------------------------------------------------------------------------
// Kernel 1: GroupNorm (blocks 0..511) + weight cvt (blocks 512..1535), fused.
// GN: single-tile, 3 barriers, -> g_ht[b][hw][c] fp16.
// ---------------------------------------------------------------------------
__global__ __launch_bounds__(256) void gn_cvt_kernel(const float* __restrict__ x,
                                                     const float* __restrict__ gamma,
                                                     const float* __restrict__ beta,
                                                     const float* __restrict__ wq,
                                                     const float* __restrict__ wp) {
    int tid = threadIdx.x;
    if (blockIdx.x >= 512) {
        int i = ((blockIdx.x - 512) * 256 + tid) * 4;
        if (i < 3 * Cc * Cc) {
            float4 v = *(const float4*)(wq + i);
            *(__half2*)(g_wqkv + i)     = __floats2half2_rn(v.x, v.y);
            *(__half2*)(g_wqkv + i + 2) = __floats2half2_rn(v.z, v.w);
        } else {
            int j = i - 3 * Cc * Cc;
            float4 v = *(const float4*)(wp + j);
            *(__half2*)(g_wproj + j)     = __floats2half2_rn(v.x, v.y);
            *(__half2*)(g_wproj + j + 2) = __floats2half2_rn(v.z, v.w);
        }
        return;
    }

    extern __shared__ float sx[];            // [16][1032]
    __shared__ float rs_[8], rss_[8];
    __shared__ float ga_s[16], be_s[16];

    int b = blockIdx.x >> 5;
    int g = blockIdx.x & 31;
    size_t base = (size_t)(b * Cc + g * 16) * HWn;
    const float4* xp = (const float4*)(x + base);

    float s = 0.f, ss = 0.f;
    for (int i = tid; i < 4096; i += 256) {
        float4 v = xp[i];
        int c = i >> 8, hw4 = i & 255;
        *(float4*)&sx[c * 1032 + hw4 * 4] = v;
        s  += v.x + v.y + v.z + v.w;
        ss += v.x * v.x + v.y * v.y + v.z * v.z + v.w * v.w;
    }
    #pragma unroll
    for (int o = 16; o; o >>= 1) {
        s  += __shfl_xor_sync(0xffffffffu, s, o);
        ss += __shfl_xor_sync(0xffffffffu, ss, o);
    }
    int wid = tid >> 5, lid = tid & 31;
    if (lid == 0) { rs_[wid] = s; rss_[wid] = ss; }
    __syncthreads();
    if (tid < 32) {
        s = rs_[lid & 7]; ss = rss_[lid & 7];
        #pragma unroll
        for (int o = 4; o; o >>= 1) {
            s  += __shfl_xor_sync(0xffffffffu, s, o);
            ss += __shfl_xor_sync(0xffffffffu, ss, o);
        }
        if (lid == 0) { rs_[0] = s; rss_[0] = ss; }
    }
    __syncthreads();
    float mean = rs_[0] * (1.f / 16384.f);
    float var  = rss_[0] * (1.f / 16384.f) - mean * mean;
    float inv  = rsqrtf(var + 1e-5f);
    if (tid < 16) {
        float ga = gamma[g * 16 + tid] * inv;
        ga_s[tid] = ga;
        be_s[tid] = beta[g * 16 + tid] - mean * ga;
    }
    __syncthreads();

    __half* outb = g_ht + (size_t)b * HWn * Cc + g * 16;
    for (int hw = tid; hw < HWn; hw += 256) {
        uint32_t pk[8];
        #pragma unroll
        for (int cp = 0; cp < 8; cp++) {
            float v0 = sx[(2 * cp) * 1032 + hw]     * ga_s[2 * cp]     + be_s[2 * cp];
            float v1 = sx[(2 * cp + 1) * 1032 + hw] * ga_s[2 * cp + 1] + be_s[2 * cp + 1];
            pk[cp] = pack_h2(v0, v1);
        }
        __half* dst = outb + (size_t)hw * Cc;
        *(uint4*)dst       = make_uint4(pk[0], pk[1], pk[2], pk[3]);
        *(uint4*)(dst + 8) = make_uint4(pk[4], pk[5], pk[6], pk[7]);
    }
}

// ---------------------------------------------------------------------------
// Kernel 2: qkv GEMM (M = s rows of h^T, N = o rows of W, 128x128 blocks).
// q pre-scaled by QSCALE; q,k -> [s][c]; v -> transposed [c][s].
// ---------------------------------------------------------------------------
__global__ __launch_bounds__(256) void qkv_mma_kernel(const float* __restrict__ bias) {
    int b = blockIdx.z, m0 = blockIdx.x * 128, n0 = blockIdx.y * 128;
    const __half* Arow = g_ht + ((size_t)b * HWn + m0) * Cc;
    const __half* Brow = g_wqkv + (size_t)n0 * Cc;
    float acc[4][4][4];
    gemm_mainloop(Arow, Brow, acc);

    const int warp = threadIdx.x >> 5, lane = threadIdx.x & 31;
    const int wm = warp & 1, wn = warp >> 1;
    const int g = lane >> 2, tig = lane & 3;
    #pragma unroll
    for (int mi = 0; mi < 4; mi++) {
        #pragma unroll
        for (int h = 0; h < 2; h++) {
            int s = m0 + wm * 64 + mi * 16 + g + h * 8;
            #pragma unroll
            for (int ni = 0; ni < 4; ni++) {
                int o = n0 + wn * 32 + ni * 8 + 2 * tig;
                float2 bv = *(const float2*)&bias[o];
                float v0 = acc[mi][ni][h * 2 + 0] + bv.x;
                float v1 = acc[mi][ni][h * 2 + 1] + bv.y;
                int head = o / 192, rem = o - head * 192;
                int part = rem >> 6, c = rem & 63;
                __half* base = g_qkv + (size_t)((b * NH + head) * 3 + part) * HWn * DH;
                if (part == 0) {
                    *(__half2*)(base + (size_t)s * DH + c) =
                        __floats2half2_rn(v0 * QSCALE, v1 * QSCALE);
                } else if (part == 1) {
                    *(__half2*)(base + (size_t)s * DH + c) = __floats2half2_rn(v0, v1);
                } else {
                    base[(size_t)c * HWn + s]       = __float2half_rn(v0);
                    base[(size_t)(c + 1) * HWn + s] = __float2half_rn(v1);
                }
            }
        }
    }
}

// ---------------------------------------------------------------------------
// Kernel 3: flash attention. 128-query blocks, 4 warps x m32, 4-stage cp.async
// K/V, Q frags from gmem, exp2 softmax w/o max. S-phase restructured (p outer,
// kk inner) so only 16 sacc regs are live -> fits 3 blocks/SM (12 warps).
// Smem 73728 B x 3 = 221 KB.
// ---------------------------------------------------------------------------
__global__ __launch_bounds__(128, 3) void attn_mma_kernel() {
    extern __shared__ char asmem[];
    uint32_t sb = smem_u32(asmem);

    int bh = blockIdx.y;
    int q0 = blockIdx.x << 7;
    int tid = threadIdx.x;
    int w = tid >> 5, lane = tid & 31;
    int g = lane >> 2, tig = lane & 3;

    const __half* qp = g_qkv + ((size_t)bh * 3 * HWn + q0) * DH;
    const __half* kp = g_qkv + (size_t)(bh * 3 + 1) * HWn * DH;
    const __half* vp = g_qkv + (size_t)(bh * 3 + 2) * HWn * DH;  // [dh][s]

    const int brow = (lane & 7) + ((lane >> 4) & 1) * 8;
    const int lkb  = ((lane >> 3) & 1) * 8;
    const uint32_t kAddr = sb + (uint32_t)(brow * 144 + lkb * 2);
    const uint32_t vAddr = sb + 36864u + (uint32_t)(brow * 144 + lkb * 2);

    #pragma unroll
    for (int st = 0; st < 3; st++) {
        const __half* kpt = kp + (size_t)st * 64 * DH;
        const __half* vpt = vp + st * 64;
        #pragma unroll
        for (int i = 0; i < 4; i++) {
            int id = tid + i * 128;
            int r = id >> 3, q = id & 7;
            CP16(sb + (uint32_t)(st * 9216 + r * 144 + q * 16),
                 kpt + (size_t)r * DH + q * 8);
            CP16(sb + 36864u + (uint32_t)(st * 9216 + r * 144 + q * 16),
                 vpt + (size_t)r * HWn + q * 8);
        }
        CP_COMMIT();
    }

    uint32_t qf[2][4][4];
    #pragma unroll
    for (int mi = 0; mi < 2; mi++) {
        const __half* qr  = qp + (size_t)(w * 32 + mi * 16 + g) * DH + 2 * tig;
        const __half* qr8 = qr + 8 * DH;
        #pragma unroll
        for (int kk = 0; kk < 4; kk++) {
            qf[mi][kk][0] = *(const uint32_t*)(qr  + kk * 16);
            qf[mi][kk][1] = *(const uint32_t*)(qr8 + kk * 16);
            qf[mi][kk][2] = *(const uint32_t*)(qr  + kk * 16 + 8);
            qf[mi][kk][3] = *(const uint32_t*)(qr8 + kk * 16 + 8);
        }
    }

    float oacc[2][8][4];
    #pragma unroll
    for (int mi = 0; mi < 2; mi++)
        #pragma unroll
        for (int nd = 0; nd < 8; nd++)
            #pragma unroll
            for (int c = 0; c < 4; c++) oacc[mi][nd][c] = 0.f;
    float l00 = 0.f, l01 = 0.f, l10 = 0.f, l11 = 0.f;

    #pragma unroll 1
    for (int t = 0; t < 16; t++) {
        if (t < 14)      { CP_WAIT2(); }
        else if (t == 14){ CP_WAIT1(); }
        else             { CP_WAIT0(); }
        __syncthreads();
        if (t + 3 < 16) {
            int st3 = (t + 3) & 3;
            const __half* kpt = kp + (size_t)(t + 3) * 64 * DH;
            const __half* vpt = vp + (t + 3) * 64;
            #pragma unroll
            for (int i = 0; i < 4; i++) {
                int id = tid + i * 128;
                int r = id >> 3, q = id & 7;
                CP16(sb + (uint32_t)(st3 * 9216 + r * 144 + q * 16),
                     kpt + (size_t)r * DH + q * 8);
                CP16(sb + 36864u + (uint32_t)(st3 * 9216 + r * 144 + q * 16),
                     vpt + (size_t)r * HWn + q * 8);
            }
            CP_COMMIT();
        }
        const uint32_t so = (uint32_t)((t & 3) * 9216);

        // ---- S = Q @ K^T, p-outer / kk-inner: only 16 sacc regs live ----
        uint32_t ph[2][8][2];
        #pragma unroll
        for (int p = 0; p < 4; p++) {
            float sacc[2][2][4];
            #pragma unroll
            for (int mi = 0; mi < 2; mi++)
                #pragma unroll
                for (int ni = 0; ni < 2; ni++)
                    #pragma unroll
                    for (int c = 0; c < 4; c++) sacc[mi][ni][c] = 0.f;
            #pragma unroll
            for (int kk = 0; kk < 4; kk++) {
                uint32_t r0, r1, r2, r3;
                LDSM_X4(r0, r1, r2, r3, kAddr + so + p * 2304 + kk * 32);
                uint32_t b0[2] = {r0, r1}, b1[2] = {r2, r3};
                #pragma unroll
                for (int mi = 0; mi < 2; mi++) {
                    MMA_F16(sacc[mi][0], qf[mi][kk], b0);
                    MMA_F16(sacc[mi][1], qf[mi][kk], b1);
                }
            }
            #pragma unroll
            for (int mi = 0; mi < 2; mi++) {
                ph[mi][2 * p][0]     = h2ex2(pack_h2(sacc[mi][0][0], sacc[mi][0][1]));
                ph[mi][2 * p][1]     = h2ex2(pack_h2(sacc[mi][0][2], sacc[mi][0][3]));
                ph[mi][2 * p + 1][0] = h2ex2(pack_h2(sacc[mi][1][0], sacc[mi][1][1]));
                ph[mi][2 * p + 1][1] = h2ex2(pack_h2(sacc[mi][1][2], sacc[mi][1][3]));
            }
        }

        // ---- row sums (hadd2 trees, per m-tile) ----
        #pragma unroll
        for (int mi = 0; mi < 2; mi++) {
            uint32_t t0 = h2add(h2add(h2add(ph[mi][0][0], ph[mi][1][0]),
                                      h2add(ph[mi][2][0], ph[mi][3][0])),
                                h2add(h2add(ph[mi][4][0], ph[mi][5][0]),
                                      h2add(ph[mi][6][0], ph[mi][7][0])));
            uint32_t t1 = h2add(h2add(h2add(ph[mi][0][1], ph[mi][1][1]),
                                      h2add(ph[mi][2][1], ph[mi][3][1])),
                                h2add(h2add(ph[mi][4][1], ph[mi][5][1]),
                                      h2add(ph[mi][6][1], ph[mi][7][1])));
            float2 f0 = h2f2(t0), f1 = h2f2(t1);
            float rs0 = f0.x + f0.y, rs1 = f1.x + f1.y;
            rs0 += __shfl_xor_sync(0xffffffffu, rs0, 1);
            rs0 += __shfl_xor_sync(0xffffffffu, rs0, 2);
            rs1 += __shfl_xor_sync(0xffffffffu, rs1, 1);
            rs1 += __shfl_xor_sync(0xffffffffu, rs1, 2);
            if (mi == 0) { l00 += rs0; l01 += rs1; }
            else         { l10 += rs0; l11 += rs1; }
        }

        // ---- O += P @ V : one V LDSM feeds both m-tiles ----
        #pragma unroll
        for (int kk = 0; kk < 4; kk++) {
            #pragma unroll
            for (int p = 0; p < 4; p++) {
                uint32_t r0, r1, r2, r3;
                LDSM_X4(r0, r1, r2, r3, vAddr + so + p * 2304 + kk * 32);
                uint32_t b0[2] = {r0, r1}, b1[2] = {r2, r3};
                #pragma unroll
                for (int mi = 0; mi < 2; mi++) {
                    uint32_t ap[4] = {ph[mi][2 * kk][0], ph[mi][2 * kk][1],
                                      ph[mi][2 * kk + 1][0], ph[mi][2 * kk + 1][1]};
                    MMA_F16(oacc[mi][2 * p],     ap, b0);
                    MMA_F16(oacc[mi][2 * p + 1], ap, b1);
                }
            }
        }
    }

    // ---- epilogue ----
    int bp  = bh & 15;
    int ch0 = (bh >> 4) << 6;
    #pragma unroll
    for (int mi = 0; mi < 2; mi++) {
        float il0 = 1.f / (mi == 0 ? l00 : l10);
        float il1 = 1.f / (mi == 0 ? l01 : l11);
        int s0 = q0 + w * 32 + mi * 16 + g;
        #pragma unroll
        for (int nd = 0; nd < 8; nd++) {
            int c = ch0 + nd * 8 + 2 * tig;
            *(__half2*)(g_attn + ((size_t)(bp * HWn + s0)) * Cc + c) =
                __floats2half2_rn(oacc[mi][nd][0] * il0, oacc[mi][nd][1] * il0);
            *(__half2*)(g_attn + ((size_t)(bp * HWn + s0 + 8)) * Cc + c) =
                __floats2half2_rn(oacc[mi][nd][2] * il1, oacc[mi][nd][3] * il1);
        }
    }
}

// ---------------------------------------------------------------------------
// Kernel 4: out = W_proj @ attn + bias + x (128x128 blocks).
// ---------------------------------------------------------------------------
__global__ __launch_bounds__(256) void proj_mma_kernel(const float* __restrict__ bias,
                                                       const float* __restrict__ x,
                                                       float* __restrict__ out) {
    int b = blockIdx.z, o0 = blockIdx.x * 128, n0 = blockIdx.y * 128;
    const __half* Arow = g_wproj + (size_t)o0 * Cc;
    const __half* Brow = g_attn + ((size_t)b * HWn + n0) * Cc;
    float acc[4][4][4];
    gemm_mainloop(Arow, Brow, acc);

    const int warp = threadIdx.x >> 5, lane = threadIdx.x & 31;
    const int wm = warp & 1, wn = warp >> 1;
    const int g = lane >> 2, tig = lane & 3;
    #pragma unroll
    for (int mi = 0; mi < 4; mi++) {
        #pragma unroll
        for (int h = 0; h < 2; h++) {
            int o = o0 + wm * 64 + mi * 16 + g + h * 8;
            float bv = __ldg(bias + o);
            size_t rowoff = (size_t)(b * Cc + o) * HWn;
            #pragma unroll
            for (int ni = 0; ni < 4; ni++) {
                int s = n0 + wn * 32 + ni * 8 + 2 * tig;
                float2 xv = *(const float2*)&x[rowoff + s];
                float2 ov;
                ov.x = acc[mi][ni][h * 2 + 0] + bv + xv.x;
                ov.y = acc[mi][ni][h * 2 + 1] + bv + xv.y;
                *(float2*)&out[rowoff + s] = ov;
            }
        }
    }
}

// ---------------------------------------------------------------------------
extern "C" void kernel_launch(void* const* d_in, const int* in_sizes, int n_in,
                              void* d_out, int out_size) {
    const float* x      = (const float*)d_in[0];
    const float* gamma  = (const float*)d_in[1];
    const float* beta   = (const float*)d_in[2];
    const float* w_qkv  = (const float*)d_in[3];
    const float* b_qkv  = (const float*)d_in[4];
    const float* w_proj = (const float*)d_in[5];
    const float* b_proj = (const float*)d_in[6];
    float* out = (float*)d_out;

    const int GEMM_SMEM = 110592;    // 3 stages x (A+B) x 128x144B
    const int ATTN_SMEM = 73728;     // 4 x (K 9216) + 4 x (V 9216)
    const int GN_SMEM   = 66048;
    cudaFuncSetAttribute(qkv_mma_kernel,
                         cudaFuncAttributeMaxDynamicSharedMemorySize, GEMM_SMEM);
    cudaFuncSetAttribute(proj_mma_kernel,
                         cudaFuncAttributeMaxDynamicSharedMemorySize, GEMM_SMEM);
    cudaFuncSetAttribute(attn_mma_kernel,
                         cudaFuncAttributeMaxDynamicSharedMemorySize, ATTN_SMEM);
    cudaFuncSetAttribute(gn_cvt_kernel,
                         cudaFuncAttributeMaxDynamicSharedMemorySize, GN_SMEM);

    gn_cvt_kernel<<<1536, 256, GN_SMEM>>>(x, gamma, beta, w_qkv, w_proj);
    qkv_mma_kernel<<<dim3(8, 12, Bn), 256, GEMM_SMEM>>>(b_qkv);
    attn_mma_kernel<<<dim3(HWn / 128, Bn * NH), 128, ATTN_SMEM>>>();
    proj_mma_kernel<<<dim3(4, 8, Bn), 256, GEMM_SMEM>>>(b_proj, x, out);
}